// round 16
// baseline (speedup 1.0000x reference)
#include <cuda_runtime.h>
#include <cuda_fp16.h>
#include <cstdint>

// ---------------- problem constants ----------------
#define B_    4
#define N_    1024
#define CIN_  256
#define HW_   256
#define D_    512
#define IN_   2304
#define ROWS_ 4096

// ---------------- device scratch ----------------
__device__ __half g_featsT[(size_t)B_ * HW_ * HW_ * CIN_]; // NHWC fp16, 128 MB
__device__ __half g_flat[(size_t)ROWS_ * IN_];             // layout: bin*256+c
__device__ __half g_w1t[(size_t)D_ * IN_];                 // K-permuted
__device__ __half g_w2t[(size_t)D_ * D_];
__device__ __half g_hid[(size_t)ROWS_ * D_];
__device__ float g_lines[(size_t)ROWS_ * D_];
__device__ float g_outt[(size_t)ROWS_ * D_];

// ---------------- helpers ----------------
#define CP_ASYNC16(dst, src) \
    asm volatile("cp.async.cg.shared.global [%0], [%1], 16;" :: "r"(dst), "l"(src))
#define CP_COMMIT() asm volatile("cp.async.commit_group;" ::: "memory")
#define CP_WAIT(n)  asm volatile("cp.async.wait_group %0;" :: "n"(n) : "memory")

__device__ __forceinline__ void mma16816(float* c, const uint32_t* a, const uint32_t* b) {
    asm volatile(
        "mma.sync.aligned.m16n8k16.row.col.f32.f16.f16.f32 "
        "{%0,%1,%2,%3}, {%4,%5,%6,%7}, {%8,%9}, {%0,%1,%2,%3};"
        : "+f"(c[0]), "+f"(c[1]), "+f"(c[2]), "+f"(c[3])
        : "r"(a[0]), "r"(a[1]), "r"(a[2]), "r"(a[3]), "r"(b[0]), "r"(b[1]));
}

__device__ __forceinline__ uint32_t pack_h2(float x, float y) {
    __half hx = __float2half_rn(x);
    __half hy = __float2half_rn(y);
    return (uint32_t)__half_as_ushort(hx) | ((uint32_t)__half_as_ushort(hy) << 16);
}

__device__ __forceinline__ float4 bbox_of(const float* __restrict__ boxes, int n) {
    float4 p0 = *(const float4*)(boxes + (size_t)n * 8);
    float4 p1 = *(const float4*)(boxes + (size_t)n * 8 + 4);
    float4 r;
    r.x = fminf(fminf(p0.x, p0.z), fminf(p1.x, p1.z));
    r.y = fminf(fminf(p0.y, p0.w), fminf(p1.y, p1.w));
    r.z = fmaxf(fmaxf(p0.x, p0.z), fmaxf(p1.x, p1.z));
    r.w = fmaxf(fmaxf(p0.y, p0.w), fmaxf(p1.y, p1.w));
    return r;
}

// ---------------- stream/event setup (static init; NOT during checkpoints)
__global__ void noop_kernel() {}

struct StreamInit {
    cudaStream_t s2;
    cudaEvent_t evStart, evFt[B_], evJoin;
    StreamInit() {
        cudaStreamCreateWithFlags(&s2, cudaStreamNonBlocking);
        cudaEventCreateWithFlags(&evStart, cudaEventDisableTiming);
        for (int i = 0; i < B_; i++)
            cudaEventCreateWithFlags(&evFt[i], cudaEventDisableTiming);
        cudaEventCreateWithFlags(&evJoin, cudaEventDisableTiming);
        // pre-warm both streams so lazy launch resources allocate now
        noop_kernel<<<1, 32>>>();
        noop_kernel<<<1, 32, 0, s2>>>();
        cudaDeviceSynchronize();
    }
};
static StreamInit g_si;

// ---------------- weights: transpose + fp16 (+perm for W1) ---------------
__global__ void wsplit_kernel(const float* __restrict__ W1,
                              const float* __restrict__ W2) {
    __shared__ float tile[32][33];
    const int z  = blockIdx.z;
    const int K  = z ? D_ : IN_;
    if (blockIdx.x * 32 >= K) return;
    const float* W = z ? W2 : W1;
    __half* T = z ? g_w2t : g_w1t;

    int j0 = blockIdx.x * 32, n0 = blockIdx.y * 32;
    int tx = threadIdx.x, ty = threadIdx.y;
#pragma unroll
    for (int i = 0; i < 4; i++) {
        int j = j0 + ty + i * 8;
        int k = z ? j : ((j & 255) * 9 + (j >> 8));
        tile[ty + i * 8][tx] = W[(size_t)k * D_ + n0 + tx];
    }
    __syncthreads();
#pragma unroll
    for (int i = 0; i < 4; i++) {
        float v = tile[tx][ty + i * 8];
        T[(size_t)(n0 + ty + i * 8) * K + j0 + tx] = __float2half_rn(v);
    }
}

// ---------------- NCHW f32 -> NHWC fp16 transpose, per-batch -------------
__global__ __launch_bounds__(256) void feat_transpose_kernel(const float* __restrict__ in,
                                                             int b) {
    __shared__ float t[32][129];
    int p0 = blockIdx.x * 128;
    int c0 = blockIdx.y * 32;
    const float* ib = in + (size_t)b * CIN_ * (HW_ * HW_);
    __half* ob = g_featsT + (size_t)b * (HW_ * HW_) * CIN_;
    const int tid = threadIdx.x;
    {
        int cy   = tid >> 5;
        int col4 = (tid & 31) * 4;
#pragma unroll
        for (int i = 0; i < 4; i++) {
            int c = cy + i * 8;
            float4 v = *(const float4*)(ib + (size_t)(c0 + c) * (HW_ * HW_) + p0 + col4);
            t[c][col4 + 0] = v.x; t[c][col4 + 1] = v.y;
            t[c][col4 + 2] = v.z; t[c][col4 + 3] = v.w;
        }
    }
    __syncthreads();
    {
        int ch8 = (tid & 3) * 8;
        int pxb = tid >> 2;
#pragma unroll
        for (int i = 0; i < 2; i++) {
            int p = pxb + i * 64;
            uint4 v;
            v.x = pack_h2(t[ch8 + 0][p], t[ch8 + 1][p]);
            v.y = pack_h2(t[ch8 + 2][p], t[ch8 + 3][p]);
            v.z = pack_h2(t[ch8 + 4][p], t[ch8 + 5][p]);
            v.w = pack_h2(t[ch8 + 6][p], t[ch8 + 7][p]);
            *(uint4*)(ob + (size_t)(p0 + p) * CIN_ + c0 + ch8) = v;
        }
    }
}

// ---------------- ROI align on fp16 feats, per-batch (R14 body) ----------
__global__ __launch_bounds__(256, 2) void roi_kernel(const float* __restrict__ boxes,
                                                     int b) {
    const int tid = threadIdx.x;
    const int grp = tid >> 6;
    const int n   = b * N_ + blockIdx.x * 4 + grp;
    const int c4  = (tid & 63) * 4;
    const __half* fb = g_featsT + (size_t)b * (HW_ * HW_) * CIN_;

    float4 bb = bbox_of(boxes, n);
    float x1 = bb.x * 0.25f, y1 = bb.y * 0.25f;
    float x2 = bb.z * 0.25f, y2 = bb.w * 0.25f;
    float binw = fmaxf(x2 - x1, 1.0f) * (1.0f / 3.0f);
    float binh = fmaxf(y2 - y1, 1.0f) * (1.0f / 3.0f);

    int   yi0[6], yi1[6], xi0[6], xi1[6];
    float yl[6], yv[6], xl[6], xv[6];
#pragma unroll
    for (int s = 0; s < 6; s++) {
        float g = 0.5f * (float)s + 0.25f;
        float yy = y1 + g * binh;
        yv[s] = (yy > -1.0f && yy < 256.0f) ? 1.0f : 0.0f;
        float yc = fminf(fmaxf(yy, 0.0f), 255.0f);
        int i0 = (int)floorf(yc);
        yi0[s] = i0; yi1[s] = min(i0 + 1, 255); yl[s] = yc - (float)i0;

        float xx = x1 + g * binw;
        xv[s] = (xx > -1.0f && xx < 256.0f) ? 1.0f : 0.0f;
        float xc = fminf(fmaxf(xx, 0.0f), 255.0f);
        int j0 = (int)floorf(xc);
        xi0[s] = j0; xi1[s] = min(j0 + 1, 255); xl[s] = xc - (float)j0;
    }

    float4 acc[9];
#pragma unroll
    for (int i = 0; i < 9; i++) acc[i] = make_float4(0.f, 0.f, 0.f, 0.f);

#pragma unroll
    for (int sy = 0; sy < 6; sy++) {
        float ly = yl[sy], hy = 1.0f - ly;
        int r0 = yi0[sy] * 256, r1 = yi1[sy] * 256;
#pragma unroll
        for (int sx = 0; sx < 6; sx++) {
            float lx = xl[sx], hx = 1.0f - lx;
            float w = 0.25f * yv[sy] * xv[sx];
            float w00 = w * hy * hx, w01 = w * hy * lx;
            float w10 = w * ly * hx, w11 = w * ly * lx;
            const __half2* p00 = (const __half2*)(fb + ((size_t)(r0 + xi0[sx])) * CIN_ + c4);
            const __half2* p01 = (const __half2*)(fb + ((size_t)(r0 + xi1[sx])) * CIN_ + c4);
            const __half2* p10 = (const __half2*)(fb + ((size_t)(r1 + xi0[sx])) * CIN_ + c4);
            const __half2* p11 = (const __half2*)(fb + ((size_t)(r1 + xi1[sx])) * CIN_ + c4);
            float2 a00 = __half22float2(p00[0]), b00 = __half22float2(p00[1]);
            float2 a01 = __half22float2(p01[0]), b01 = __half22float2(p01[1]);
            float2 a10 = __half22float2(p10[0]), b10 = __half22float2(p10[1]);
            float2 a11 = __half22float2(p11[0]), b11 = __half22float2(p11[1]);
            int bin = (sy >> 1) * 3 + (sx >> 1);
            acc[bin].x += a00.x * w00 + a01.x * w01 + a10.x * w10 + a11.x * w11;
            acc[bin].y += a00.y * w00 + a01.y * w01 + a10.y * w10 + a11.y * w11;
            acc[bin].z += b00.x * w00 + b01.x * w01 + b10.x * w10 + b11.x * w11;
            acc[bin].w += b00.y * w00 + b01.y * w01 + b10.y * w10 + b11.y * w11;
        }
    }

    size_t base = (size_t)n * IN_;
#pragma unroll
    for (int i = 0; i < 9; i++) {
        uint32_t p0 = pack_h2(acc[i].x, acc[i].y);
        uint32_t p1 = pack_h2(acc[i].z, acc[i].w);
        *(uint2*)(g_flat + base + i * 256 + c4) = make_uint2(p0, p1);
    }
}

// ---------------- GEMM: mma.sync fp16 single-term, 128x128x32 (R12) ------
#define SROW 40
#define A_T  (128 * SROW * 2)            // 10240 B
#define B_T  (128 * SROW * 2)            // 10240 B
#define STAGE (A_T + B_T)                // 20480 B  [A|B]

template <int MODE>
__global__ __launch_bounds__(256, 1) void mma_gemm_kernel(const float* __restrict__ bias) {
    constexpr int K  = (MODE == 0) ? IN_ : D_;
    constexpr int KT = K / 32;

    const __half* A  = (MODE == 0) ? g_flat : g_hid;
    const __half* Bw = (MODE == 0) ? g_w1t : g_w2t;

    extern __shared__ __align__(16) char smem[];   // 2 * STAGE = 40960
    const uint32_t sbase = (uint32_t)__cvta_generic_to_shared(smem);

    const int tid  = threadIdx.x;
    const int wid  = tid >> 5, lane = tid & 31;
    const int g    = lane >> 2, tg = lane & 3;
    const int wm   = wid >> 2, wn = wid & 3;       // 2 x 4 warps; warp = 64m x 32n
    const int bm   = blockIdx.y * 128;
    const int bn   = blockIdx.x * 128;

    float acc[4][4][4];
#pragma unroll
    for (int i = 0; i < 4; i++)
#pragma unroll
        for (int j = 0; j < 4; j++)
#pragma unroll
            for (int q = 0; q < 4; q++) acc[i][j][q] = 0.0f;

    auto load_tile = [&](int kt, int s) {
        int kk = kt * 32;
        uint32_t sb = sbase + s * STAGE;
#pragma unroll
        for (int i = 0; i < 2; i++) {
            int id = tid + i * 256;
            int r = id >> 2, ch = id & 3;
            uint32_t off = r * (SROW * 2) + ch * 16;
            size_t gof = (size_t)r * K + kk + ch * 8;
            CP_ASYNC16(sb + off,       (const char*)(A  + (size_t)bm * K + gof));
            CP_ASYNC16(sb + A_T + off, (const char*)(Bw + (size_t)bn * K + gof));
        }
    };

    load_tile(0, 0);
    CP_COMMIT();

    int buf = 0;
    for (int kt = 0; kt < KT; kt++) {
        if (kt + 1 < KT) { load_tile(kt + 1, buf ^ 1); CP_COMMIT(); }
        if (kt + 1 < KT) { CP_WAIT(1); } else { CP_WAIT(0); }
        __syncthreads();

        const char* stg = smem + buf * STAGE;
        const __half* Ah = (const __half*)(stg);
        const __half* Bh = (const __half*)(stg + A_T);

#pragma unroll
        for (int k16 = 0; k16 < 32; k16 += 16) {
            uint32_t bfr[4][2];
#pragma unroll
            for (int nt = 0; nt < 4; nt++) {
                const __half* p = Bh + (size_t)(wn * 32 + nt * 8 + g) * SROW + k16 + tg * 2;
                bfr[nt][0] = *(const uint32_t*)(p);
                bfr[nt][1] = *(const uint32_t*)(p + 8);
            }
            uint32_t a[4][4];
#pragma unroll
            for (int mt = 0; mt < 4; mt++) {
                const __half* p = Ah + (size_t)(wm * 64 + mt * 16 + g) * SROW + k16 + tg * 2;
                a[mt][0] = *(const uint32_t*)(p);
                a[mt][1] = *(const uint32_t*)(p + 8 * SROW);
                a[mt][2] = *(const uint32_t*)(p + 8);
                a[mt][3] = *(const uint32_t*)(p + 8 * SROW + 8);
            }
#pragma unroll
            for (int mt = 0; mt < 4; mt++)
#pragma unroll
                for (int nt = 0; nt < 4; nt++)
                    mma16816(acc[mt][nt], a[mt], bfr[nt]);
        }
        __syncthreads();
        buf ^= 1;
    }

    // ---------------- epilogue ----------------
#pragma unroll
    for (int mt = 0; mt < 4; mt++) {
        const int row = bm + wm * 64 + mt * 16 + g;
#pragma unroll
        for (int nt = 0; nt < 4; nt++) {
            const int col = bn + wn * 32 + nt * 8 + 2 * tg;
            float bc0 = bias[col], bc1 = bias[col + 1];
            float v0 = acc[mt][nt][0] + bc0;
            float v1 = acc[mt][nt][1] + bc1;
            float v2 = acc[mt][nt][2] + bc0;
            float v3 = acc[mt][nt][3] + bc1;
            if (MODE == 0) {
                v0 = fmaxf(v0, 0.0f); v1 = fmaxf(v1, 0.0f);
                v2 = fmaxf(v2, 0.0f); v3 = fmaxf(v3, 0.0f);
                *(uint32_t*)(g_hid + (size_t)row * D_ + col)       = pack_h2(v0, v1);
                *(uint32_t*)(g_hid + (size_t)(row + 8) * D_ + col) = pack_h2(v2, v3);
            } else {
                *(float2*)(g_lines + (size_t)row * D_ + col)       = make_float2(v0, v1);
                *(float2*)(g_lines + (size_t)(row + 8) * D_ + col) = make_float2(v2, v3);
            }
        }
    }
}

// ---------------- posln (+ masks) ----------------
__device__ __forceinline__ float2 block_reduce2(float v0, float v1) {
    __shared__ float s0[16], s1[16];
    int lane = threadIdx.x & 31, wid = threadIdx.x >> 5;
    __syncthreads();
#pragma unroll
    for (int o = 16; o > 0; o >>= 1) {
        v0 += __shfl_down_sync(0xffffffffu, v0, o);
        v1 += __shfl_down_sync(0xffffffffu, v1, o);
    }
    if (lane == 0) { s0[wid] = v0; s1[wid] = v1; }
    __syncthreads();
    if (wid == 0) {
        v0 = (lane < 16) ? s0[lane] : 0.0f;
        v1 = (lane < 16) ? s1[lane] : 0.0f;
#pragma unroll
        for (int o = 8; o > 0; o >>= 1) {
            v0 += __shfl_down_sync(0xffffffffu, v0, o);
            v1 += __shfl_down_sync(0xffffffffu, v1, o);
        }
        if (lane == 0) { s0[0] = v0; s1[0] = v1; }
    }
    __syncthreads();
    return make_float2(s0[0], s1[0]);
}

__global__ __launch_bounds__(512) void posln_kernel(
    const float* __restrict__ img_sizes, const float* __restrict__ boxes,
    const float* __restrict__ Wb, const float* __restrict__ bbv,
    const float* __restrict__ g1, const float* __restrict__ be1,
    const float* __restrict__ g2, const float* __restrict__ be2,
    float* __restrict__ masks) {
    int n = blockIdx.x;
    int b = n >> 10;
    int d = threadIdx.x;

    float4 bb = bbox_of(boxes, n);
    float s0 = __ldg(img_sizes + 2 * b), s1 = __ldg(img_sizes + 2 * b + 1);
    float q0 = bb.x / s0, q1 = bb.y / s1, q2 = bb.z / s0, q3 = bb.w / s1;

    float p = bbv[d] + q0 * Wb[d] + q1 * Wb[D_ + d] + q2 * Wb[2 * D_ + d] + q3 * Wb[3 * D_ + d];
    float2 r = block_reduce2(p, p * p);
    float mu  = r.x * (1.0f / D_);
    float var = r.y * (1.0f / D_) - mu * mu;
    float pos = (p - mu) * rsqrtf(var + 1e-5f) * g1[d] + be1[d];

    float sf = g_lines[(size_t)n * D_ + d] + pos;
    r = block_reduce2(sf, sf * sf);
    mu  = r.x * (1.0f / D_);
    var = r.y * (1.0f / D_) - mu * mu;
    float o = (sf - mu) * rsqrtf(var + 1e-5f) * g2[d] + be2[d];
    g_outt[(size_t)n * D_ + d] = o;

    if (d == 0) masks[n] = 1.0f;
}

// ---------------- (B,N,D) -> (B,D,N) ----------------
__global__ void out_transpose_kernel(float* __restrict__ out) {
    __shared__ float tile[32][33];
    int b  = blockIdx.z;
    int n0 = blockIdx.x * 32;
    int d0 = blockIdx.y * 32;
    int tx = threadIdx.x, ty = threadIdx.y;
#pragma unroll
    for (int i = 0; i < 4; i++)
        tile[ty + i * 8][tx] = g_outt[((size_t)(b << 10) + n0 + ty + i * 8) * D_ + d0 + tx];
    __syncthreads();
#pragma unroll
    for (int i = 0; i < 4; i++)
        out[((size_t)b * D_ + d0 + ty + i * 8) * N_ + n0 + tx] = tile[tx][ty + i * 8];
}

// ---------------- launch ----------------
extern "C" void kernel_launch(void* const* d_in, const int* in_sizes, int n_in,
                              void* d_out, int out_size) {
    const float* feats     = (const float*)d_in[0];
    const float* boxes     = (const float*)d_in[1];
    const float* img_sizes = (const float*)d_in[2];
    const float* W1 = (const float*)d_in[3];
    const float* b1 = (const float*)d_in[4];
    const float* W2 = (const float*)d_in[5];
    const float* b2 = (const float*)d_in[6];
    const float* Wb = (const float*)d_in[7];
    const float* bb = (const float*)d_in[8];
    const float* g1 = (const float*)d_in[9];
    const float* be1 = (const float*)d_in[10];
    const float* g2 = (const float*)d_in[11];
    const float* be2 = (const float*)d_in[12];
    float* out = (float*)d_out;

    const int gsmem = 2 * STAGE;   // 40960
    cudaFuncSetAttribute(mma_gemm_kernel<0>, cudaFuncAttributeMaxDynamicSharedMemorySize, gsmem);
    cudaFuncSetAttribute(mma_gemm_kernel<1>, cudaFuncAttributeMaxDynamicSharedMemorySize, gsmem);

    cudaStream_t s2 = g_si.s2;

    // fork side stream into the capture DAG
    cudaEventRecord(g_si.evStart, 0);
    cudaStreamWaitEvent(s2, g_si.evStart, 0);

    // side stream: weights (independent), then per-batch roi after its ft
    wsplit_kernel<<<dim3(IN_ / 32, D_ / 32, 2), dim3(32, 8), 0, s2>>>(W1, W2);

    for (int b = 0; b < B_; b++) {
        feat_transpose_kernel<<<dim3(512, 8, 1), 256>>>(feats, b);      // stream 0
        cudaEventRecord(g_si.evFt[b], 0);
        cudaStreamWaitEvent(s2, g_si.evFt[b], 0);
        roi_kernel<<<N_ / 4, 256, 0, s2>>>(boxes, b);                   // stream s2
    }

    // join side stream back into stream 0
    cudaEventRecord(g_si.evJoin, s2);
    cudaStreamWaitEvent(0, g_si.evJoin, 0);

    mma_gemm_kernel<0><<<dim3(D_ / 128, ROWS_ / 128), 256, gsmem>>>(b1);
    mma_gemm_kernel<1><<<dim3(D_ / 128, ROWS_ / 128), 256, gsmem>>>(b2);
    posln_kernel<<<ROWS_, 512>>>(img_sizes, boxes, Wb, bb, g1, be1, g2, be2,
                                 out + (size_t)B_ * D_ * N_);
    out_transpose_kernel<<<dim3(32, 16, 4), dim3(32, 8)>>>(out);
}

// round 17
// speedup vs baseline: 1.2698x; 1.2698x over previous
#include <cuda_runtime.h>
#include <cuda_fp16.h>
#include <cstdint>

// ---------------- problem constants ----------------
#define B_    4
#define N_    1024
#define CIN_  256
#define HW_   256
#define D_    512
#define IN_   2304
#define ROWS_ 4096

// ---------------- device scratch ----------------
__device__ __half g_featsT[(size_t)B_ * HW_ * HW_ * CIN_]; // NHWC fp16, 128 MB
__device__ __half g_flat[(size_t)ROWS_ * IN_];             // layout: bin*256+c
__device__ __half g_w1t[(size_t)D_ * IN_];                 // K-permuted
__device__ __half g_w2t[(size_t)D_ * D_];
__device__ __half g_hid[(size_t)ROWS_ * D_];
__device__ float g_lines[(size_t)ROWS_ * D_];
__device__ float g_outt[(size_t)ROWS_ * D_];

// ---------------- helpers ----------------
#define CP_ASYNC16(dst, src) \
    asm volatile("cp.async.cg.shared.global [%0], [%1], 16;" :: "r"(dst), "l"(src))
#define CP_COMMIT() asm volatile("cp.async.commit_group;" ::: "memory")
#define CP_WAIT(n)  asm volatile("cp.async.wait_group %0;" :: "n"(n) : "memory")

__device__ __forceinline__ void mma16816(float* c, const uint32_t* a, const uint32_t* b) {
    asm volatile(
        "mma.sync.aligned.m16n8k16.row.col.f32.f16.f16.f32 "
        "{%0,%1,%2,%3}, {%4,%5,%6,%7}, {%8,%9}, {%0,%1,%2,%3};"
        : "+f"(c[0]), "+f"(c[1]), "+f"(c[2]), "+f"(c[3])
        : "r"(a[0]), "r"(a[1]), "r"(a[2]), "r"(a[3]), "r"(b[0]), "r"(b[1]));
}

__device__ __forceinline__ uint32_t pack_h2(float x, float y) {
    __half hx = __float2half_rn(x);
    __half hy = __float2half_rn(y);
    return (uint32_t)__half_as_ushort(hx) | ((uint32_t)__half_as_ushort(hy) << 16);
}

__device__ __forceinline__ float4 bbox_of(const float* __restrict__ boxes, int n) {
    float4 p0 = *(const float4*)(boxes + (size_t)n * 8);
    float4 p1 = *(const float4*)(boxes + (size_t)n * 8 + 4);
    float4 r;
    r.x = fminf(fminf(p0.x, p0.z), fminf(p1.x, p1.z));
    r.y = fminf(fminf(p0.y, p0.w), fminf(p1.y, p1.w));
    r.z = fmaxf(fmaxf(p0.x, p0.z), fmaxf(p1.x, p1.z));
    r.w = fmaxf(fmaxf(p0.y, p0.w), fmaxf(p1.y, p1.w));
    return r;
}

// ---------------- masks = 1 ----------------
__global__ void masks_kernel(float* __restrict__ m) {
    int i = blockIdx.x * blockDim.x + threadIdx.x;
    if (i < B_ * N_) m[i] = 1.0f;
}

// ---------------- NCHW f32 -> NHWC fp16 transpose (monolithic, R14) ------
__global__ __launch_bounds__(256) void feat_transpose_kernel(const float* __restrict__ in) {
    __shared__ float t[32][129];
    int b  = blockIdx.z;
    int p0 = blockIdx.x * 128;
    int c0 = blockIdx.y * 32;
    const float* ib = in + (size_t)b * CIN_ * (HW_ * HW_);
    __half* ob = g_featsT + (size_t)b * (HW_ * HW_) * CIN_;
    const int tid = threadIdx.x;
    {
        int cy   = tid >> 5;
        int col4 = (tid & 31) * 4;
#pragma unroll
        for (int i = 0; i < 4; i++) {
            int c = cy + i * 8;
            float4 v = *(const float4*)(ib + (size_t)(c0 + c) * (HW_ * HW_) + p0 + col4);
            t[c][col4 + 0] = v.x; t[c][col4 + 1] = v.y;
            t[c][col4 + 2] = v.z; t[c][col4 + 3] = v.w;
        }
    }
    __syncthreads();
    {
        int ch8 = (tid & 3) * 8;
        int pxb = tid >> 2;
#pragma unroll
        for (int i = 0; i < 2; i++) {
            int p = pxb + i * 64;
            uint4 v;
            v.x = pack_h2(t[ch8 + 0][p], t[ch8 + 1][p]);
            v.y = pack_h2(t[ch8 + 2][p], t[ch8 + 3][p]);
            v.z = pack_h2(t[ch8 + 4][p], t[ch8 + 5][p]);
            v.w = pack_h2(t[ch8 + 6][p], t[ch8 + 7][p]);
            *(uint4*)(ob + (size_t)(p0 + p) * CIN_ + c0 + ch8) = v;
        }
    }
}

// ---------------- weights: transpose + fp16 (+perm for W1) ---------------
__global__ void wsplit_kernel(const float* __restrict__ W1,
                              const float* __restrict__ W2) {
    __shared__ float tile[32][33];
    const int z  = blockIdx.z;
    const int K  = z ? D_ : IN_;
    if (blockIdx.x * 32 >= K) return;
    const float* W = z ? W2 : W1;
    __half* T = z ? g_w2t : g_w1t;

    int j0 = blockIdx.x * 32, n0 = blockIdx.y * 32;
    int tx = threadIdx.x, ty = threadIdx.y;
#pragma unroll
    for (int i = 0; i < 4; i++) {
        int j = j0 + ty + i * 8;
        int k = z ? j : ((j & 255) * 9 + (j >> 8));
        tile[ty + i * 8][tx] = W[(size_t)k * D_ + n0 + tx];
    }
    __syncthreads();
#pragma unroll
    for (int i = 0; i < 4; i++) {
        float v = tile[tx][ty + i * 8];
        T[(size_t)(n0 + ty + i * 8) * K + j0 + tx] = __float2half_rn(v);
    }
}

// ---------------- ROI align: full half2 arithmetic -----------------------
__global__ __launch_bounds__(256, 2) void roi_kernel(const float* __restrict__ boxes) {
    const int tid = threadIdx.x;
    const int grp = tid >> 6;
    const int n   = blockIdx.x * 4 + grp;
    const int b   = n >> 10;
    const int c4  = (tid & 63) * 4;
    const __half* fb = g_featsT + (size_t)b * (HW_ * HW_) * CIN_;

    float4 bb = bbox_of(boxes, n);
    float x1 = bb.x * 0.25f, y1 = bb.y * 0.25f;
    float x2 = bb.z * 0.25f, y2 = bb.w * 0.25f;
    float binw = fmaxf(x2 - x1, 1.0f) * (1.0f / 3.0f);
    float binh = fmaxf(y2 - y1, 1.0f) * (1.0f / 3.0f);

    int   yi0[6], yi1[6], xi0[6], xi1[6];
    float yl[6], yv[6], xl[6], xv[6];
#pragma unroll
    for (int s = 0; s < 6; s++) {
        float g = 0.5f * (float)s + 0.25f;
        float yy = y1 + g * binh;
        yv[s] = (yy > -1.0f && yy < 256.0f) ? 1.0f : 0.0f;
        float yc = fminf(fmaxf(yy, 0.0f), 255.0f);
        int i0 = (int)floorf(yc);
        yi0[s] = i0; yi1[s] = min(i0 + 1, 255); yl[s] = yc - (float)i0;

        float xx = x1 + g * binw;
        xv[s] = (xx > -1.0f && xx < 256.0f) ? 1.0f : 0.0f;
        float xc = fminf(fmaxf(xx, 0.0f), 255.0f);
        int j0 = (int)floorf(xc);
        xi0[s] = j0; xi1[s] = min(j0 + 1, 255); xl[s] = xc - (float)j0;
    }

    __half2 acc[9][2];
#pragma unroll
    for (int i = 0; i < 9; i++) {
        acc[i][0] = __float2half2_rn(0.0f);
        acc[i][1] = __float2half2_rn(0.0f);
    }

#pragma unroll
    for (int sy = 0; sy < 6; sy++) {
        float ly = yl[sy], hy = 1.0f - ly;
        int r0 = yi0[sy] * 256, r1 = yi1[sy] * 256;
#pragma unroll
        for (int sx = 0; sx < 6; sx++) {
            float lx = xl[sx], hx = 1.0f - lx;
            float w = 0.25f * yv[sy] * xv[sx];
            __half2 w00 = __float2half2_rn(w * hy * hx);
            __half2 w01 = __float2half2_rn(w * hy * lx);
            __half2 w10 = __float2half2_rn(w * ly * hx);
            __half2 w11 = __float2half2_rn(w * ly * lx);
            const __half2* p00 = (const __half2*)(fb + ((size_t)(r0 + xi0[sx])) * CIN_ + c4);
            const __half2* p01 = (const __half2*)(fb + ((size_t)(r0 + xi1[sx])) * CIN_ + c4);
            const __half2* p10 = (const __half2*)(fb + ((size_t)(r1 + xi0[sx])) * CIN_ + c4);
            const __half2* p11 = (const __half2*)(fb + ((size_t)(r1 + xi1[sx])) * CIN_ + c4);
            int bin = (sy >> 1) * 3 + (sx >> 1);
#pragma unroll
            for (int h = 0; h < 2; h++) {
                __half2 v = __hmul2(p00[h], w00);
                v = __hfma2(p01[h], w01, v);
                v = __hfma2(p10[h], w10, v);
                v = __hfma2(p11[h], w11, v);
                acc[bin][h] = __hadd2(acc[bin][h], v);
            }
        }
    }

    size_t base = (size_t)n * IN_;
#pragma unroll
    for (int i = 0; i < 9; i++) {
        uint2 v;
        v.x = *(uint32_t*)&acc[i][0];
        v.y = *(uint32_t*)&acc[i][1];
        *(uint2*)(g_flat + base + i * 256 + c4) = v;
    }
}

// ---------------- GEMM: mma.sync fp16 single-term, 128x128x32 (R12) ------
#define SROW 40
#define A_T  (128 * SROW * 2)            // 10240 B
#define B_T  (128 * SROW * 2)            // 10240 B
#define STAGE (A_T + B_T)                // 20480 B  [A|B]

template <int MODE>
__global__ __launch_bounds__(256, 1) void mma_gemm_kernel(const float* __restrict__ bias) {
    constexpr int K  = (MODE == 0) ? IN_ : D_;
    constexpr int KT = K / 32;

    const __half* A  = (MODE == 0) ? g_flat : g_hid;
    const __half* Bw = (MODE == 0) ? g_w1t : g_w2t;

    extern __shared__ __align__(16) char smem[];   // 2 * STAGE = 40960
    const uint32_t sbase = (uint32_t)__cvta_generic_to_shared(smem);

    const int tid  = threadIdx.x;
    const int wid  = tid >> 5, lane = tid & 31;
    const int g    = lane >> 2, tg = lane & 3;
    const int wm   = wid >> 2, wn = wid & 3;       // 2 x 4 warps; warp = 64m x 32n
    const int bm   = blockIdx.y * 128;
    const int bn   = blockIdx.x * 128;

    float acc[4][4][4];
#pragma unroll
    for (int i = 0; i < 4; i++)
#pragma unroll
        for (int j = 0; j < 4; j++)
#pragma unroll
            for (int q = 0; q < 4; q++) acc[i][j][q] = 0.0f;

    auto load_tile = [&](int kt, int s) {
        int kk = kt * 32;
        uint32_t sb = sbase + s * STAGE;
#pragma unroll
        for (int i = 0; i < 2; i++) {
            int id = tid + i * 256;
            int r = id >> 2, ch = id & 3;
            uint32_t off = r * (SROW * 2) + ch * 16;
            size_t gof = (size_t)r * K + kk + ch * 8;
            CP_ASYNC16(sb + off,       (const char*)(A  + (size_t)bm * K + gof));
            CP_ASYNC16(sb + A_T + off, (const char*)(Bw + (size_t)bn * K + gof));
        }
    };

    load_tile(0, 0);
    CP_COMMIT();

    int buf = 0;
    for (int kt = 0; kt < KT; kt++) {
        if (kt + 1 < KT) { load_tile(kt + 1, buf ^ 1); CP_COMMIT(); }
        if (kt + 1 < KT) { CP_WAIT(1); } else { CP_WAIT(0); }
        __syncthreads();

        const char* stg = smem + buf * STAGE;
        const __half* Ah = (const __half*)(stg);
        const __half* Bh = (const __half*)(stg + A_T);

#pragma unroll
        for (int k16 = 0; k16 < 32; k16 += 16) {
            uint32_t bfr[4][2];
#pragma unroll
            for (int nt = 0; nt < 4; nt++) {
                const __half* p = Bh + (size_t)(wn * 32 + nt * 8 + g) * SROW + k16 + tg * 2;
                bfr[nt][0] = *(const uint32_t*)(p);
                bfr[nt][1] = *(const uint32_t*)(p + 8);
            }
            uint32_t a[4][4];
#pragma unroll
            for (int mt = 0; mt < 4; mt++) {
                const __half* p = Ah + (size_t)(wm * 64 + mt * 16 + g) * SROW + k16 + tg * 2;
                a[mt][0] = *(const uint32_t*)(p);
                a[mt][1] = *(const uint32_t*)(p + 8 * SROW);
                a[mt][2] = *(const uint32_t*)(p + 8);
                a[mt][3] = *(const uint32_t*)(p + 8 * SROW + 8);
            }
#pragma unroll
            for (int mt = 0; mt < 4; mt++)
#pragma unroll
                for (int nt = 0; nt < 4; nt++)
                    mma16816(acc[mt][nt], a[mt], bfr[nt]);
        }
        __syncthreads();
        buf ^= 1;
    }

    // ---------------- epilogue ----------------
#pragma unroll
    for (int mt = 0; mt < 4; mt++) {
        const int row = bm + wm * 64 + mt * 16 + g;
#pragma unroll
        for (int nt = 0; nt < 4; nt++) {
            const int col = bn + wn * 32 + nt * 8 + 2 * tg;
            float bc0 = bias[col], bc1 = bias[col + 1];
            float v0 = acc[mt][nt][0] + bc0;
            float v1 = acc[mt][nt][1] + bc1;
            float v2 = acc[mt][nt][2] + bc0;
            float v3 = acc[mt][nt][3] + bc1;
            if (MODE == 0) {
                v0 = fmaxf(v0, 0.0f); v1 = fmaxf(v1, 0.0f);
                v2 = fmaxf(v2, 0.0f); v3 = fmaxf(v3, 0.0f);
                *(uint32_t*)(g_hid + (size_t)row * D_ + col)       = pack_h2(v0, v1);
                *(uint32_t*)(g_hid + (size_t)(row + 8) * D_ + col) = pack_h2(v2, v3);
            } else {
                *(float2*)(g_lines + (size_t)row * D_ + col)       = make_float2(v0, v1);
                *(float2*)(g_lines + (size_t)(row + 8) * D_ + col) = make_float2(v2, v3);
            }
        }
    }
}

// ---------------- posln ----------------
__device__ __forceinline__ float2 block_reduce2(float v0, float v1) {
    __shared__ float s0[16], s1[16];
    int lane = threadIdx.x & 31, wid = threadIdx.x >> 5;
    __syncthreads();
#pragma unroll
    for (int o = 16; o > 0; o >>= 1) {
        v0 += __shfl_down_sync(0xffffffffu, v0, o);
        v1 += __shfl_down_sync(0xffffffffu, v1, o);
    }
    if (lane == 0) { s0[wid] = v0; s1[wid] = v1; }
    __syncthreads();
    if (wid == 0) {
        v0 = (lane < 16) ? s0[lane] : 0.0f;
        v1 = (lane < 16) ? s1[lane] : 0.0f;
#pragma unroll
        for (int o = 8; o > 0; o >>= 1) {
            v0 += __shfl_down_sync(0xffffffffu, v0, o);
            v1 += __shfl_down_sync(0xffffffffu, v1, o);
        }
        if (lane == 0) { s0[0] = v0; s1[0] = v1; }
    }
    __syncthreads();
    return make_float2(s0[0], s1[0]);
}

__global__ __launch_bounds__(512) void posln_kernel(
    const float* __restrict__ img_sizes, const float* __restrict__ boxes,
    const float* __restrict__ Wb, const float* __restrict__ bbv,
    const float* __restrict__ g1, const float* __restrict__ be1,
    const float* __restrict__ g2, const float* __restrict__ be2) {
    int n = blockIdx.x;
    int b = n >> 10;
    int d = threadIdx.x;

    float4 bb = bbox_of(boxes, n);
    float s0 = __ldg(img_sizes + 2 * b), s1 = __ldg(img_sizes + 2 * b + 1);
    float q0 = bb.x / s0, q1 = bb.y / s1, q2 = bb.z / s0, q3 = bb.w / s1;

    float p = bbv[d] + q0 * Wb[d] + q1 * Wb[D_ + d] + q2 * Wb[2 * D_ + d] + q3 * Wb[3 * D_ + d];
    float2 r = block_reduce2(p, p * p);
    float mu  = r.x * (1.0f / D_);
    float var = r.y * (1.0f / D_) - mu * mu;
    float pos = (p - mu) * rsqrtf(var + 1e-5f) * g1[d] + be1[d];

    float sf = g_lines[(size_t)n * D_ + d] + pos;
    r = block_reduce2(sf, sf * sf);
    mu  = r.x * (1.0f / D_);
    var = r.y * (1.0f / D_) - mu * mu;
    float o = (sf - mu) * rsqrtf(var + 1e-5f) * g2[d] + be2[d];
    g_outt[(size_t)n * D_ + d] = o;
}

// ---------------- (B,N,D) -> (B,D,N) ----------------
__global__ void out_transpose_kernel(float* __restrict__ out) {
    __shared__ float tile[32][33];
    int b  = blockIdx.z;
    int n0 = blockIdx.x * 32;
    int d0 = blockIdx.y * 32;
    int tx = threadIdx.x, ty = threadIdx.y;
#pragma unroll
    for (int i = 0; i < 4; i++)
        tile[ty + i * 8][tx] = g_outt[((size_t)(b << 10) + n0 + ty + i * 8) * D_ + d0 + tx];
    __syncthreads();
#pragma unroll
    for (int i = 0; i < 4; i++)
        out[((size_t)b * D_ + d0 + ty + i * 8) * N_ + n0 + tx] = tile[tx][ty + i * 8];
}

// ---------------- launch ----------------
extern "C" void kernel_launch(void* const* d_in, const int* in_sizes, int n_in,
                              void* d_out, int out_size) {
    const float* feats     = (const float*)d_in[0];
    const float* boxes     = (const float*)d_in[1];
    const float* img_sizes = (const float*)d_in[2];
    const float* W1 = (const float*)d_in[3];
    const float* b1 = (const float*)d_in[4];
    const float* W2 = (const float*)d_in[5];
    const float* b2 = (const float*)d_in[6];
    const float* Wb = (const float*)d_in[7];
    const float* bb = (const float*)d_in[8];
    const float* g1 = (const float*)d_in[9];
    const float* be1 = (const float*)d_in[10];
    const float* g2 = (const float*)d_in[11];
    const float* be2 = (const float*)d_in[12];
    float* out = (float*)d_out;

    const int gsmem = 2 * STAGE;   // 40960
    cudaFuncSetAttribute(mma_gemm_kernel<0>, cudaFuncAttributeMaxDynamicSharedMemorySize, gsmem);
    cudaFuncSetAttribute(mma_gemm_kernel<1>, cudaFuncAttributeMaxDynamicSharedMemorySize, gsmem);

    masks_kernel<<<16, 256>>>(out + (size_t)B_ * D_ * N_);                         // 1
    feat_transpose_kernel<<<dim3(512, 8, 4), 256>>>(feats);                        // 2
    wsplit_kernel<<<dim3(IN_ / 32, D_ / 32, 2), dim3(32, 8)>>>(W1, W2);            // 3
    roi_kernel<<<ROWS_ / 4, 256>>>(boxes);                                         // 4 <- profiled
    mma_gemm_kernel<0><<<dim3(D_ / 128, ROWS_ / 128), 256, gsmem>>>(b1);           // 5
    mma_gemm_kernel<1><<<dim3(D_ / 128, ROWS_ / 128), 256, gsmem>>>(b2);           // 6
    posln_kernel<<<ROWS_, 512>>>(img_sizes, boxes, Wb, bb, g1, be1, g2, be2);      // 7
    out_transpose_kernel<<<dim3(32, 16, 4), dim3(32, 8)>>>(out);                   // 8
}